// round 7
// baseline (speedup 1.0000x reference)
#include <cuda_runtime.h>
#include <math.h>

#define B_    8
#define M_    1026
#define NT_   1024
#define C_    384
#define H_    6
#define D_    64
#define HID_  1536
#define W_    256
#define CAT_  257
#define SCALE_ 0.4082482904638631f

// ---------------------------------------------------------------------------
// Scratch
// ---------------------------------------------------------------------------
__device__ float g_h1  [B_*M_*C_];
__device__ float g_qkv [B_*M_*3*C_];
__device__ float g_att [B_*M_*C_];
__device__ float g_res [B_*M_*C_];
__device__ float g_h2  [B_*(NT_+1)*C_];
__device__ float g_cat [B_*CAT_*C_];
__device__ float g_h3  [B_*CAT_*C_];
__device__ float g_fc1 [B_*CAT_*HID_];
__device__ float g_clsp[48*8*66];        // CLS split-K partials: m, s, o[64]

// ---------------------------------------------------------------------------
// Helpers
// ---------------------------------------------------------------------------
__device__ __forceinline__ float warpSum(float v) {
#pragma unroll
    for (int o = 16; o > 0; o >>= 1) v += __shfl_xor_sync(0xffffffffu, v, o);
    return v;
}
__device__ __forceinline__ float warpMax(float v) {
#pragma unroll
    for (int o = 16; o > 0; o >>= 1) v = fmaxf(v, __shfl_xor_sync(0xffffffffu, v, o));
    return v;
}
__device__ __forceinline__ unsigned f2tf(float f) {
    unsigned u;
    asm("cvt.rna.tf32.f32 %0, %1;" : "=r"(u) : "f"(f));
    return u;
}
__device__ __forceinline__ void cpasync16(void* smem_dst, const void* gsrc, bool pred) {
    unsigned saddr = (unsigned)__cvta_generic_to_shared(smem_dst);
    int sz = pred ? 16 : 0;
    asm volatile("cp.async.ca.shared.global [%0], [%1], 16, %2;\n"
                 :: "r"(saddr), "l"(gsrc), "r"(sz));
}

// ---------------------------------------------------------------------------
// LayerNorm; rows >= inRows emit zeros
// ---------------------------------------------------------------------------
__global__ void ln_kernel(const float* __restrict__ in, float* __restrict__ out,
                          const float* __restrict__ gw, const float* __restrict__ gb,
                          int inStride, int outStride, int inRows) {
    int i = blockIdx.x, b = blockIdx.y;
    int tid = threadIdx.x;
    float* yr = out + ((size_t)b * outStride + i) * C_;
    if (i >= inRows) {
        yr[tid] = 0.f; yr[tid + 128] = 0.f; yr[tid + 256] = 0.f;
        return;
    }
    const float* xr = in + ((size_t)b * inStride + i) * C_;
    float v0 = xr[tid], v1 = xr[tid + 128], v2 = xr[tid + 256];
    __shared__ float sm[4];
    float s = warpSum(v0 + v1 + v2);
    if ((tid & 31) == 0) sm[tid >> 5] = s;
    __syncthreads();
    float mu = (sm[0] + sm[1] + sm[2] + sm[3]) * (1.f / 384.f);
    float d0 = v0 - mu, d1 = v1 - mu, d2 = v2 - mu;
    __syncthreads();
    float q = warpSum(d0 * d0 + d1 * d1 + d2 * d2);
    if ((tid & 31) == 0) sm[tid >> 5] = q;
    __syncthreads();
    float var = (sm[0] + sm[1] + sm[2] + sm[3]) * (1.f / 384.f);
    float rs = rsqrtf(var + 1e-5f);
    yr[tid]       = d0 * rs * gw[tid]       + gb[tid];
    yr[tid + 128] = d1 * rs * gw[tid + 128] + gb[tid + 128];
    yr[tid + 256] = d2 * rs * gw[tid + 256] + gb[tid + 256];
}

// ---------------------------------------------------------------------------
// TF32 tensor-core GEMM. 128x64x32 CTA tile, 128 threads = 4 warps (2m x 2n),
// warp tile 64x32 (fragments a[4][4], b[4][2] -> 1.5 LDS/MMA).
// 2-stage cp.async pipeline.
// gatherMode: A row (b*256+w), col (kk*384+c) -> g_h2[b, hrow(w,kk), c].
// catMode: output row remap row -> row + row/256 + 1 (pool -> g_cat).
// ---------------------------------------------------------------------------
#define KP_ 36
#define TG_SMEM ((2*128*KP_ + 2*64*KP_) * 4)   // 55296 bytes

__global__ void __launch_bounds__(128)
tgemm_kernel(int M, int N, int K,
             const float* __restrict__ A, const float* __restrict__ Wt,
             const float* __restrict__ bias, const float* __restrict__ resid,
             float* __restrict__ Cc, int doGelu, int gatherMode, int catMode) {
    extern __shared__ float dyn[];
    float (*sA)[128][KP_] = (float(*)[128][KP_])dyn;
    float (*sB)[64][KP_]  = (float(*)[64][KP_])(dyn + 2 * 128 * KP_);

    int tid  = threadIdx.x;
    int lane = tid & 31;
    int wid  = tid >> 5;      // 0..3
    int wm   = wid & 1;       // m offset 64*wm
    int wn   = wid >> 1;      // n offset 32*wn
    int lr   = lane >> 2;
    int lc   = lane & 3;

    int bm = blockIdx.y * 128;
    int bn = blockIdx.x * 64;

    int ldRow = tid >> 3;     // 0..15
    int ldC4  = tid & 7;      // 0..7

    float acc[4][4][4];
#pragma unroll
    for (int mt = 0; mt < 4; ++mt)
#pragma unroll
        for (int nt = 0; nt < 4; ++nt)
#pragma unroll
            for (int e = 0; e < 4; ++e) acc[mt][nt][e] = 0.f;

    int nIter = K >> 5;

    auto loadTile = [&](int it, int s) {
        int k0 = it << 5;
        if (!gatherMode) {
#pragma unroll
            for (int i = 0; i < 8; ++i) {
                int r = ldRow + i * 16;
                int gr = bm + r;
                bool p = gr < M;
                const float* src = A + (size_t)(p ? gr : 0) * K + k0 + ldC4 * 4;
                cpasync16(&sA[s][r][ldC4 * 4], src, p);
            }
        } else {
            int kk = k0 / 384;
            int c0 = k0 - kk * 384;
#pragma unroll
            for (int i = 0; i < 8; ++i) {
                int r = ldRow + i * 16;
                int gr = bm + r;
                int b = gr >> 8, w = gr & 255;
                int wi = w >> 4, wj = w & 15;
                int rr = 2 * wi + kk / 3 - 1;
                int cc = 2 * wj + kk % 3 - 1;
                int hrow = (rr < 0 || cc < 0) ? 1024 : rr * 32 + cc + 1;
                const float* src = A + ((size_t)b * 1025 + hrow) * 384 + c0 + ldC4 * 4;
                cpasync16(&sA[s][r][ldC4 * 4], src, true);
            }
        }
#pragma unroll
        for (int i = 0; i < 4; ++i) {
            int n = ldRow + i * 16;
            int gn = bn + n;
            bool p = gn < N;
            const float* src = Wt + (size_t)(p ? gn : 0) * K + k0 + ldC4 * 4;
            cpasync16(&sB[s][n][ldC4 * 4], src, p);
        }
    };

    loadTile(0, 0);
    asm volatile("cp.async.commit_group;\n");

    for (int it = 0; it < nIter; ++it) {
        int s = it & 1;
        if (it + 1 < nIter) {
            loadTile(it + 1, s ^ 1);
            asm volatile("cp.async.commit_group;\n");
            asm volatile("cp.async.wait_group 1;\n");
        } else {
            asm volatile("cp.async.wait_group 0;\n");
        }
        __syncthreads();

#pragma unroll
        for (int ks = 0; ks < 4; ++ks) {
            int kk = ks * 8;
            unsigned a[4][4], bf[4][2];
#pragma unroll
            for (int mt = 0; mt < 4; ++mt) {
                int row = wm * 64 + mt * 16 + lr;
                a[mt][0] = f2tf(sA[s][row    ][kk + lc]);
                a[mt][1] = f2tf(sA[s][row + 8][kk + lc]);
                a[mt][2] = f2tf(sA[s][row    ][kk + lc + 4]);
                a[mt][3] = f2tf(sA[s][row + 8][kk + lc + 4]);
            }
#pragma unroll
            for (int nt = 0; nt < 4; ++nt) {
                int n = wn * 32 + nt * 8 + lr;
                bf[nt][0] = f2tf(sB[s][n][kk + lc]);
                bf[nt][1] = f2tf(sB[s][n][kk + lc + 4]);
            }
#pragma unroll
            for (int mt = 0; mt < 4; ++mt)
#pragma unroll
                for (int nt = 0; nt < 4; ++nt) {
                    asm volatile(
                        "mma.sync.aligned.m16n8k8.row.col.f32.tf32.tf32.f32 "
                        "{%0,%1,%2,%3}, {%4,%5,%6,%7}, {%8,%9}, {%0,%1,%2,%3};\n"
                        : "+f"(acc[mt][nt][0]), "+f"(acc[mt][nt][1]),
                          "+f"(acc[mt][nt][2]), "+f"(acc[mt][nt][3])
                        : "r"(a[mt][0]), "r"(a[mt][1]), "r"(a[mt][2]), "r"(a[mt][3]),
                          "r"(bf[nt][0]), "r"(bf[nt][1]));
                }
        }
        __syncthreads();
    }

    // ---- epilogue ----
#pragma unroll
    for (int mt = 0; mt < 4; ++mt) {
#pragma unroll
        for (int nt = 0; nt < 4; ++nt) {
            int col = bn + wn * 32 + nt * 8 + 2 * lc;
            float bx = 0.f, by = 0.f;
            if (bias) { bx = bias[col]; by = bias[col + 1]; }
#pragma unroll
            for (int half = 0; half < 2; ++half) {
                int row = bm + wm * 64 + mt * 16 + lr + half * 8;
                if (row >= M) continue;
                float vx = acc[mt][nt][2 * half + 0] + bx;
                float vy = acc[mt][nt][2 * half + 1] + by;
                if (resid) {
                    const float2 rv = *(const float2*)(resid + (size_t)row * N + col);
                    vx += rv.x; vy += rv.y;
                }
                if (doGelu) {
                    vx = 0.5f * vx * (1.f + erff(vx * 0.70710678118654752f));
                    vy = 0.5f * vy * (1.f + erff(vy * 0.70710678118654752f));
                }
                int orow = catMode ? (row + (row >> 8) + 1) : row;
                *(float2*)(Cc + (size_t)orow * N + col) = make_float2(vx, vy);
            }
        }
    }
}

// ---------------------------------------------------------------------------
// Sparse attention (token queries): one warp per (b,h,t), split-warp QK.
// ---------------------------------------------------------------------------
__global__ void attn_token_kernel() {
    int gw = (blockIdx.x * blockDim.x + threadIdx.x) >> 5;
    int lane = threadIdx.x & 31;
    int t  = gw & 1023;
    int bh = gw >> 10;
    int h = bh % H_;
    int b = bh / H_;
    int r = t >> 5, c = t & 31;

    int rl[5], cl[5];
    int nr = 0, nc = 0;
#pragma unroll
    for (int dr = -2; dr <= 2; ++dr) {
        int rp = r + dr;
        if (rp < 0 || rp > 31) continue;
        int lo = (r > rp ? r : rp) - 1; if (lo < 0) lo = 0;
        int hi = (r < rp ? r : rp) + 1; if (hi > 30) hi = 30;
        int fe = lo + (lo & 1);
        if (fe <= hi) rl[nr++] = rp;
    }
#pragma unroll
    for (int dc = -2; dc <= 2; ++dc) {
        int cp = c + dc;
        if (cp < 0 || cp > 31) continue;
        int lo = (c > cp ? c : cp) - 1; if (lo < 0) lo = 0;
        int hi = (c < cp ? c : cp) + 1; if (hi > 30) hi = 30;
        int fe = lo + (lo & 1);
        if (fe <= hi) cl[nc++] = cp;
    }
    int cnt = 1 + nr * nc;
    int key = 0;
    if (lane >= 1 && lane < cnt) {
        int j = lane - 1;
        key = rl[j / nc] * 32 + cl[j % nc] + 1;
    }

    const float* qp = g_qkv + ((size_t)b * M_ + (t + 1)) * (3 * C_) + h * D_;
    int hl = lane & 15;
    float4 qv = *(const float4*)(qp + hl * 4);
    const float* kbase = g_qkv + (size_t)b * M_ * (3 * C_) + C_ + h * D_;

    float s = -INFINITY;
    for (int j0 = 0; j0 < 26; j0 += 2) {
        if (j0 >= cnt) break;
        int ka = __shfl_sync(0xffffffffu, key, j0);
        int kb = __shfl_sync(0xffffffffu, key, j0 + 1);
        int kidx = (lane < 16) ? ka : kb;
        float4 kv = *(const float4*)(kbase + (size_t)kidx * (3 * C_) + hl * 4);
        float d = qv.x * kv.x + qv.y * kv.y + qv.z * kv.z + qv.w * kv.w;
        d += __shfl_xor_sync(0xffffffffu, d, 8);
        d += __shfl_xor_sync(0xffffffffu, d, 4);
        d += __shfl_xor_sync(0xffffffffu, d, 2);
        d += __shfl_xor_sync(0xffffffffu, d, 1);
        float dx = __shfl_xor_sync(0xffffffffu, d, 16);
        float da = (lane < 16) ? d : dx;
        float db = (lane < 16) ? dx : d;
        if (lane == j0)     s = da * SCALE_;
        if (lane == j0 + 1) s = db * SCALE_;
    }
    if (lane >= cnt) s = -INFINITY;

    float m = fmaxf(warpMax(s), 0.f);
    float p = (lane < cnt) ? expf(s - m) : 0.f;
    float denom = warpSum(p) + expf(-m);
    float inv = 1.f / denom;

    const float* vbase = g_qkv + (size_t)b * M_ * (3 * C_) + 2 * C_ + h * D_;
    float o0 = 0.f, o1 = 0.f;
    for (int j = 0; j < cnt; ++j) {
        float pj = __shfl_sync(0xffffffffu, p, j);
        int   kj = __shfl_sync(0xffffffffu, key, j);
        float2 vv = *(const float2*)(vbase + (size_t)kj * (3 * C_) + 2 * lane);
        o0 += pj * vv.x;
        o1 += pj * vv.y;
    }
    float* op = g_att + ((size_t)b * M_ + (t + 1)) * C_ + h * D_;
    *(float2*)(op + 2 * lane) = make_float2(o0 * inv, o1 * inv);
}

// ---------------------------------------------------------------------------
// CLS attention, split-K.
// ---------------------------------------------------------------------------
__global__ void attn_cls_part_kernel() {
    int chunk = blockIdx.x;          // 0..7
    int bh    = blockIdx.y;          // 0..47
    int b = bh / H_, h = bh % H_;
    int start = chunk * 129;
    int end   = start + 129; if (end > 1025) end = 1025;
    int cnt   = end - start;
    int tid = threadIdx.x;           // 128

    __shared__ float sq[64];
    __shared__ float sc[132];
    __shared__ float sred[4];
    __shared__ float oacc[128];

    const float* qp = g_qkv + (size_t)(b * M_) * (3 * C_) + h * D_;
    if (tid < 64) sq[tid] = qp[tid];
    __syncthreads();

    for (int j = tid; j < cnt; j += 128) {
        const float* kp = g_qkv + ((size_t)b * M_ + start + j) * (3 * C_) + C_ + h * D_;
        float acc = 0.f;
#pragma unroll
        for (int d0 = 0; d0 < D_; d0 += 4) {
            float4 kv = *(const float4*)(kp + d0);
            acc += sq[d0] * kv.x + sq[d0 + 1] * kv.y + sq[d0 + 2] * kv.z + sq[d0 + 3] * kv.w;
        }
        sc[j] = acc * SCALE_;
    }
    __syncthreads();

    float m = -INFINITY;
    for (int j = tid; j < cnt; j += 128) m = fmaxf(m, sc[j]);
    m = warpMax(m);
    if ((tid & 31) == 0) sred[tid >> 5] = m;
    __syncthreads();
    m = fmaxf(fmaxf(sred[0], sred[1]), fmaxf(sred[2], sred[3]));
    __syncthreads();

    float ls = 0.f;
    for (int j = tid; j < cnt; j += 128) {
        float pv = expf(sc[j] - m);
        sc[j] = pv;
        ls += pv;
    }
    ls = warpSum(ls);
    if ((tid & 31) == 0) sred[tid >> 5] = ls;
    __syncthreads();
    float ssum = sred[0] + sred[1] + sred[2] + sred[3];

    int d = tid & 63, grp = tid >> 6;
    float acc = 0.f;
    for (int j = grp; j < cnt; j += 2)
        acc += sc[j] * g_qkv[((size_t)b * M_ + start + j) * (3 * C_) + 2 * C_ + h * D_ + d];
    oacc[tid] = acc;
    __syncthreads();

    float* dst = g_clsp + ((size_t)bh * 8 + chunk) * 66;
    if (tid < 64) dst[2 + tid] = oacc[tid] + oacc[tid + 64];
    if (tid == 0) { dst[0] = m; dst[1] = ssum; }
}

__global__ void attn_cls_comb_kernel() {
    int bh = blockIdx.x;             // 0..47
    int b = bh / H_, h = bh % H_;
    int d = threadIdx.x;             // 64
    const float* src = g_clsp + (size_t)bh * 8 * 66;
    float M = 0.f;
#pragma unroll
    for (int c = 0; c < 8; ++c) M = fmaxf(M, src[c * 66]);
    float denom = expf(-M);
    float o = 0.f;
#pragma unroll
    for (int c = 0; c < 8; ++c) {
        float w = expf(src[c * 66] - M);
        denom += src[c * 66 + 1] * w;
        o += src[c * 66 + 2 + d] * w;
    }
    g_att[(size_t)(b * M_) * C_ + h * D_ + d] = o / denom;
}

// Pad query: parallel over rows. grid (12, B), block 256.
__global__ void attn_pad_kernel() {
    int b = blockIdx.y;
    int cg = blockIdx.x;
    int tid = threadIdx.x;
    int cl = tid & 31;
    int rg = tid >> 5;
    int ch = cg * 32 + cl;
    const float* base = g_qkv + (size_t)b * M_ * (3 * C_) + 2 * C_ + ch;
    float acc = 0.f;
    for (int mrow = rg; mrow < 1025; mrow += 8)
        acc += base[(size_t)mrow * (3 * C_)];
    __shared__ float sm2[8][32];
    sm2[rg][cl] = acc;
    __syncthreads();
    if (tid < 32) {
        float a = 0.f;
#pragma unroll
        for (int rr = 0; rr < 8; ++rr) a += sm2[rr][tid];
        g_att[((size_t)b * M_ + 1025) * C_ + cg * 32 + tid] = a * (1.0f / 1026.0f);
    }
}

// Copy CLS rows of g_h2 into g_cat row 0 of each batch.
__global__ void cls_copy_kernel() {
    int b = blockIdx.x;
    int t = threadIdx.x;
    ((float4*)(g_cat + (size_t)b * CAT_ * C_))[t] =
        ((const float4*)(g_h2 + (size_t)b * 1025 * C_))[t];
}

// ---------------------------------------------------------------------------
// Launch
// ---------------------------------------------------------------------------
extern "C" void kernel_launch(void* const* d_in, const int* in_sizes, int n_in,
                              void* d_out, int out_size) {
    const float* x      = (const float*)d_in[0];
    const float* n1w    = (const float*)d_in[1];
    const float* n1b    = (const float*)d_in[2];
    const float* qkv_w  = (const float*)d_in[3];
    const float* proj_w = (const float*)d_in[4];
    const float* proj_b = (const float*)d_in[5];
    const float* n2w    = (const float*)d_in[6];
    const float* n2b    = (const float*)d_in[7];
    const float* pool_w = (const float*)d_in[8];
    const float* pool_b = (const float*)d_in[9];
    const float* n3w    = (const float*)d_in[10];
    const float* n3b    = (const float*)d_in[11];
    const float* fc1_w  = (const float*)d_in[12];
    const float* fc1_b  = (const float*)d_in[13];
    const float* fc2_w  = (const float*)d_in[14];
    const float* fc2_b  = (const float*)d_in[15];
    float* out = (float*)d_out;

    float *h1, *qkvp, *att, *res, *h2, *cat, *h3, *fc1o;
    cudaGetSymbolAddress((void**)&h1,   g_h1);
    cudaGetSymbolAddress((void**)&qkvp, g_qkv);
    cudaGetSymbolAddress((void**)&att,  g_att);
    cudaGetSymbolAddress((void**)&res,  g_res);
    cudaGetSymbolAddress((void**)&h2,   g_h2);
    cudaGetSymbolAddress((void**)&cat,  g_cat);
    cudaGetSymbolAddress((void**)&h3,   g_h3);
    cudaGetSymbolAddress((void**)&fc1o, g_fc1);

    static int smemSet = 0;
    if (!smemSet) {
        cudaFuncSetAttribute(tgemm_kernel,
                             cudaFuncAttributeMaxDynamicSharedMemorySize, TG_SMEM);
        smemSet = 1;
    }

    const int MROWS = B_ * M_;        // 8208
    const int PROWS = B_ * W_;        // 2048
    const int CROWS = B_ * CAT_;      // 2056

    // LN1 with fused pad-row zeroing
    ln_kernel<<<dim3(1026, B_), 128>>>(x, h1, n1w, n1b, 1025, M_, 1025);

    tgemm_kernel<<<dim3(1152 / 64, (MROWS + 127) / 128), 128, TG_SMEM>>>(
        MROWS, 3 * C_, C_, h1, qkv_w, nullptr, nullptr, qkvp, 0, 0, 0);

    attn_token_kernel<<<(B_ * H_ * NT_) / 8, 256>>>();
    attn_cls_part_kernel<<<dim3(8, B_ * H_), 128>>>();
    attn_cls_comb_kernel<<<B_ * H_, 64>>>();
    attn_pad_kernel<<<dim3(12, B_), 256>>>();

    tgemm_kernel<<<dim3(C_ / 64, (MROWS + 127) / 128), 128, TG_SMEM>>>(
        MROWS, C_, C_, att, proj_w, proj_b, h1, res, 0, 0, 0);

    ln_kernel<<<dim3(1025, B_), 128>>>(res, h2, n2w, n2b, M_, 1025, 1025);

    // pool GEMM with fused window gather; writes into g_cat rows 1..256
    tgemm_kernel<<<dim3(C_ / 64, PROWS / 128), 128, TG_SMEM>>>(
        PROWS, C_, 9 * C_, h2, pool_w, pool_b, nullptr, cat, 0, 1, 1);
    cls_copy_kernel<<<B_, 96>>>();

    ln_kernel<<<dim3(CAT_, B_), 128>>>(cat, h3, n3w, n3b, CAT_, CAT_, CAT_);

    tgemm_kernel<<<dim3(HID_ / 64, (CROWS + 127) / 128), 128, TG_SMEM>>>(
        CROWS, HID_, C_, h3, fc1_w, fc1_b, nullptr, fc1o, 1, 0, 0);
    tgemm_kernel<<<dim3(C_ / 64, (CROWS + 127) / 128), 128, TG_SMEM>>>(
        CROWS, C_, HID_, fc1o, fc2_w, fc2_b, nullptr, out, 0, 0, 0);
}

// round 8
// speedup vs baseline: 1.2305x; 1.2305x over previous
#include <cuda_runtime.h>
#include <math.h>

#define B_    8
#define M_    1026
#define NT_   1024
#define C_    384
#define H_    6
#define D_    64
#define HID_  1536
#define W_    256
#define CAT_  257
#define SCALE_ 0.4082482904638631f

// ---------------------------------------------------------------------------
// Scratch
// ---------------------------------------------------------------------------
__device__ float g_h1  [B_*M_*C_];
__device__ float g_qkv [B_*M_*3*C_];
__device__ float g_att [B_*M_*C_];
__device__ float g_res [B_*M_*C_];
__device__ float g_h2  [B_*(NT_+1)*C_];
__device__ float g_tok [B_*W_*C_];
__device__ float g_cat [B_*CAT_*C_];
__device__ float g_h3  [B_*CAT_*C_];
__device__ float g_fc1 [B_*CAT_*HID_];
__device__ float g_clsp[48*8*66];        // CLS split-K partials: m, s, o[64]

// ---------------------------------------------------------------------------
// Helpers
// ---------------------------------------------------------------------------
__device__ __forceinline__ float warpSum(float v) {
#pragma unroll
    for (int o = 16; o > 0; o >>= 1) v += __shfl_xor_sync(0xffffffffu, v, o);
    return v;
}
__device__ __forceinline__ float warpMax(float v) {
#pragma unroll
    for (int o = 16; o > 0; o >>= 1) v = fmaxf(v, __shfl_xor_sync(0xffffffffu, v, o));
    return v;
}
__device__ __forceinline__ unsigned f2tf(float f) {
    unsigned u;
    asm("cvt.rna.tf32.f32 %0, %1;" : "=r"(u) : "f"(f));
    return u;
}
__device__ __forceinline__ void cpasync16(void* smem_dst, const void* gsrc, bool pred) {
    unsigned saddr = (unsigned)__cvta_generic_to_shared(smem_dst);
    int sz = pred ? 16 : 0;
    asm volatile("cp.async.ca.shared.global [%0], [%1], 16, %2;\n"
                 :: "r"(saddr), "l"(gsrc), "r"(sz));
}

// ---------------------------------------------------------------------------
// LayerNorm (round-3 exact)
// ---------------------------------------------------------------------------
__global__ void ln_kernel(const float* __restrict__ in, float* __restrict__ out,
                          const float* __restrict__ gw, const float* __restrict__ gb,
                          int inStride, int outStride) {
    int i = blockIdx.x, b = blockIdx.y;
    const float* xr = in + ((size_t)b * inStride + i) * C_;
    float* yr = out + ((size_t)b * outStride + i) * C_;
    int tid = threadIdx.x;
    float v0 = xr[tid], v1 = xr[tid + 128], v2 = xr[tid + 256];
    __shared__ float sm[4];
    float s = warpSum(v0 + v1 + v2);
    if ((tid & 31) == 0) sm[tid >> 5] = s;
    __syncthreads();
    float mu = (sm[0] + sm[1] + sm[2] + sm[3]) * (1.f / 384.f);
    float d0 = v0 - mu, d1 = v1 - mu, d2 = v2 - mu;
    __syncthreads();
    float q = warpSum(d0 * d0 + d1 * d1 + d2 * d2);
    if ((tid & 31) == 0) sm[tid >> 5] = q;
    __syncthreads();
    float var = (sm[0] + sm[1] + sm[2] + sm[3]) * (1.f / 384.f);
    float rs = rsqrtf(var + 1e-5f);
    yr[tid]       = d0 * rs * gw[tid]       + gb[tid];
    yr[tid + 128] = d1 * rs * gw[tid + 128] + gb[tid + 128];
    yr[tid + 256] = d2 * rs * gw[tid + 256] + gb[tid + 256];
}

__global__ void zero_pad_kernel() {
    g_h1[((size_t)blockIdx.x * M_ + 1025) * C_ + threadIdx.x] = 0.f;
}

// ---------------------------------------------------------------------------
// TF32 tensor-core GEMM (round-3 exact): 128x64x32, 256 threads, 2-stage
// cp.async, warp tile 32x32 via m16n8k8.
// gatherMode: A row (b*256+w), col (kk*384+c) -> g_h2[b, hrow(w,kk), c].
// ---------------------------------------------------------------------------
#define KP_ 36
#define TG_SMEM ((2*128*KP_ + 2*64*KP_) * 4)   // 55296 bytes

__global__ void __launch_bounds__(256)
tgemm_kernel(int M, int N, int K,
             const float* __restrict__ A, const float* __restrict__ Wt,
             const float* __restrict__ bias, const float* __restrict__ resid,
             float* __restrict__ Cc, int doGelu, int gatherMode) {
    extern __shared__ float dyn[];
    float (*sA)[128][KP_] = (float(*)[128][KP_])dyn;
    float (*sB)[64][KP_]  = (float(*)[64][KP_])(dyn + 2 * 128 * KP_);

    int tid  = threadIdx.x;
    int lane = tid & 31;
    int wid  = tid >> 5;
    int wm   = wid & 3;
    int wn   = wid >> 2;
    int lr   = lane >> 2;
    int lc   = lane & 3;

    int bm = blockIdx.y * 128;
    int bn = blockIdx.x * 64;

    int ldRow = tid >> 3;   // 0..31
    int ldC4  = tid & 7;    // 0..7

    float acc[2][4][4];
#pragma unroll
    for (int mt = 0; mt < 2; ++mt)
#pragma unroll
        for (int nt = 0; nt < 4; ++nt)
#pragma unroll
            for (int e = 0; e < 4; ++e) acc[mt][nt][e] = 0.f;

    int nIter = K >> 5;

    auto loadTile = [&](int it, int s) {
        int k0 = it << 5;
        if (!gatherMode) {
#pragma unroll
            for (int i = 0; i < 4; ++i) {
                int r = ldRow + i * 32;
                int gr = bm + r;
                bool p = gr < M;
                const float* src = A + (size_t)(p ? gr : 0) * K + k0 + ldC4 * 4;
                cpasync16(&sA[s][r][ldC4 * 4], src, p);
            }
        } else {
            int kk = k0 / 384;
            int c0 = k0 - kk * 384;
#pragma unroll
            for (int i = 0; i < 4; ++i) {
                int r = ldRow + i * 32;
                int gr = bm + r;
                int b = gr >> 8, w = gr & 255;
                int wi = w >> 4, wj = w & 15;
                int rr = 2 * wi + kk / 3 - 1;
                int cc = 2 * wj + kk % 3 - 1;
                int hrow = (rr < 0 || cc < 0) ? 1024 : rr * 32 + cc + 1;
                const float* src = A + ((size_t)b * 1025 + hrow) * 384 + c0 + ldC4 * 4;
                cpasync16(&sA[s][r][ldC4 * 4], src, true);
            }
        }
#pragma unroll
        for (int i = 0; i < 2; ++i) {
            int n = ldRow + i * 32;
            int gn = bn + n;
            bool p = gn < N;
            const float* src = Wt + (size_t)(p ? gn : 0) * K + k0 + ldC4 * 4;
            cpasync16(&sB[s][n][ldC4 * 4], src, p);
        }
    };

    loadTile(0, 0);
    asm volatile("cp.async.commit_group;\n");

    for (int it = 0; it < nIter; ++it) {
        int s = it & 1;
        if (it + 1 < nIter) {
            loadTile(it + 1, s ^ 1);
            asm volatile("cp.async.commit_group;\n");
            asm volatile("cp.async.wait_group 1;\n");
        } else {
            asm volatile("cp.async.wait_group 0;\n");
        }
        __syncthreads();

#pragma unroll
        for (int ks = 0; ks < 4; ++ks) {
            int kk = ks * 8;
            unsigned a[2][4], bf[4][2];
#pragma unroll
            for (int mt = 0; mt < 2; ++mt) {
                int row = wm * 32 + mt * 16 + lr;
                a[mt][0] = f2tf(sA[s][row    ][kk + lc]);
                a[mt][1] = f2tf(sA[s][row + 8][kk + lc]);
                a[mt][2] = f2tf(sA[s][row    ][kk + lc + 4]);
                a[mt][3] = f2tf(sA[s][row + 8][kk + lc + 4]);
            }
#pragma unroll
            for (int nt = 0; nt < 4; ++nt) {
                int n = wn * 32 + nt * 8 + lr;
                bf[nt][0] = f2tf(sB[s][n][kk + lc]);
                bf[nt][1] = f2tf(sB[s][n][kk + lc + 4]);
            }
#pragma unroll
            for (int mt = 0; mt < 2; ++mt)
#pragma unroll
                for (int nt = 0; nt < 4; ++nt) {
                    asm volatile(
                        "mma.sync.aligned.m16n8k8.row.col.f32.tf32.tf32.f32 "
                        "{%0,%1,%2,%3}, {%4,%5,%6,%7}, {%8,%9}, {%0,%1,%2,%3};\n"
                        : "+f"(acc[mt][nt][0]), "+f"(acc[mt][nt][1]),
                          "+f"(acc[mt][nt][2]), "+f"(acc[mt][nt][3])
                        : "r"(a[mt][0]), "r"(a[mt][1]), "r"(a[mt][2]), "r"(a[mt][3]),
                          "r"(bf[nt][0]), "r"(bf[nt][1]));
                }
        }
        __syncthreads();
    }

#pragma unroll
    for (int mt = 0; mt < 2; ++mt) {
#pragma unroll
        for (int nt = 0; nt < 4; ++nt) {
            int col = bn + wn * 32 + nt * 8 + 2 * lc;
            float bx = 0.f, by = 0.f;
            if (bias) { bx = bias[col]; by = bias[col + 1]; }
#pragma unroll
            for (int half = 0; half < 2; ++half) {
                int row = bm + wm * 32 + mt * 16 + lr + half * 8;
                if (row >= M) continue;
                float vx = acc[mt][nt][2 * half + 0] + bx;
                float vy = acc[mt][nt][2 * half + 1] + by;
                if (resid) {
                    const float2 rv = *(const float2*)(resid + (size_t)row * N + col);
                    vx += rv.x; vy += rv.y;
                }
                if (doGelu) {
                    vx = 0.5f * vx * (1.f + erff(vx * 0.70710678118654752f));
                    vy = 0.5f * vy * (1.f + erff(vy * 0.70710678118654752f));
                }
                *(float2*)(Cc + (size_t)row * N + col) = make_float2(vx, vy);
            }
        }
    }
}

// ---------------------------------------------------------------------------
// Sparse attention (token queries): one warp per (b,h,t), split-warp QK
// (validated: dropped attn_token below 35us).
// ---------------------------------------------------------------------------
__global__ void attn_token_kernel() {
    int gw = (blockIdx.x * blockDim.x + threadIdx.x) >> 5;
    int lane = threadIdx.x & 31;
    int t  = gw & 1023;
    int bh = gw >> 10;
    int h = bh % H_;
    int b = bh / H_;
    int r = t >> 5, c = t & 31;

    int rl[5], cl[5];
    int nr = 0, nc = 0;
#pragma unroll
    for (int dr = -2; dr <= 2; ++dr) {
        int rp = r + dr;
        if (rp < 0 || rp > 31) continue;
        int lo = (r > rp ? r : rp) - 1; if (lo < 0) lo = 0;
        int hi = (r < rp ? r : rp) + 1; if (hi > 30) hi = 30;
        int fe = lo + (lo & 1);
        if (fe <= hi) rl[nr++] = rp;
    }
#pragma unroll
    for (int dc = -2; dc <= 2; ++dc) {
        int cp = c + dc;
        if (cp < 0 || cp > 31) continue;
        int lo = (c > cp ? c : cp) - 1; if (lo < 0) lo = 0;
        int hi = (c < cp ? c : cp) + 1; if (hi > 30) hi = 30;
        int fe = lo + (lo & 1);
        if (fe <= hi) cl[nc++] = cp;
    }
    int cnt = 1 + nr * nc;
    int key = 0;
    if (lane >= 1 && lane < cnt) {
        int j = lane - 1;
        key = rl[j / nc] * 32 + cl[j % nc] + 1;
    }

    const float* qp = g_qkv + ((size_t)b * M_ + (t + 1)) * (3 * C_) + h * D_;
    int hl = lane & 15;
    float4 qv = *(const float4*)(qp + hl * 4);
    const float* kbase = g_qkv + (size_t)b * M_ * (3 * C_) + C_ + h * D_;

    float s = -INFINITY;
    for (int j0 = 0; j0 < 26; j0 += 2) {
        if (j0 >= cnt) break;
        int ka = __shfl_sync(0xffffffffu, key, j0);
        int kb = __shfl_sync(0xffffffffu, key, j0 + 1);
        int kidx = (lane < 16) ? ka : kb;
        float4 kv = *(const float4*)(kbase + (size_t)kidx * (3 * C_) + hl * 4);
        float d = qv.x * kv.x + qv.y * kv.y + qv.z * kv.z + qv.w * kv.w;
        d += __shfl_xor_sync(0xffffffffu, d, 8);
        d += __shfl_xor_sync(0xffffffffu, d, 4);
        d += __shfl_xor_sync(0xffffffffu, d, 2);
        d += __shfl_xor_sync(0xffffffffu, d, 1);
        float dx = __shfl_xor_sync(0xffffffffu, d, 16);
        float da = (lane < 16) ? d : dx;
        float db = (lane < 16) ? dx : d;
        if (lane == j0)     s = da * SCALE_;
        if (lane == j0 + 1) s = db * SCALE_;
    }
    if (lane >= cnt) s = -INFINITY;

    float m = fmaxf(warpMax(s), 0.f);
    float p = (lane < cnt) ? expf(s - m) : 0.f;
    float denom = warpSum(p) + expf(-m);
    float inv = 1.f / denom;

    const float* vbase = g_qkv + (size_t)b * M_ * (3 * C_) + 2 * C_ + h * D_;
    float o0 = 0.f, o1 = 0.f;
    for (int j = 0; j < cnt; ++j) {
        float pj = __shfl_sync(0xffffffffu, p, j);
        int   kj = __shfl_sync(0xffffffffu, key, j);
        float2 vv = *(const float2*)(vbase + (size_t)kj * (3 * C_) + 2 * lane);
        o0 += pj * vv.x;
        o1 += pj * vv.y;
    }
    float* op = g_att + ((size_t)b * M_ + (t + 1)) * C_ + h * D_;
    *(float2*)(op + 2 * lane) = make_float2(o0 * inv, o1 * inv);
}

// ---------------------------------------------------------------------------
// CLS attention, split-K (validated: 35.8 -> 16.6us).
// ---------------------------------------------------------------------------
__global__ void attn_cls_part_kernel() {
    int chunk = blockIdx.x;          // 0..7
    int bh    = blockIdx.y;          // 0..47
    int b = bh / H_, h = bh % H_;
    int start = chunk * 129;
    int end   = start + 129; if (end > 1025) end = 1025;
    int cnt   = end - start;
    int tid = threadIdx.x;           // 128

    __shared__ float sq[64];
    __shared__ float sc[132];
    __shared__ float sred[4];
    __shared__ float oacc[128];

    const float* qp = g_qkv + (size_t)(b * M_) * (3 * C_) + h * D_;
    if (tid < 64) sq[tid] = qp[tid];
    __syncthreads();

    for (int j = tid; j < cnt; j += 128) {
        const float* kp = g_qkv + ((size_t)b * M_ + start + j) * (3 * C_) + C_ + h * D_;
        float acc = 0.f;
#pragma unroll
        for (int d0 = 0; d0 < D_; d0 += 4) {
            float4 kv = *(const float4*)(kp + d0);
            acc += sq[d0] * kv.x + sq[d0 + 1] * kv.y + sq[d0 + 2] * kv.z + sq[d0 + 3] * kv.w;
        }
        sc[j] = acc * SCALE_;
    }
    __syncthreads();

    float m = -INFINITY;
    for (int j = tid; j < cnt; j += 128) m = fmaxf(m, sc[j]);
    m = warpMax(m);
    if ((tid & 31) == 0) sred[tid >> 5] = m;
    __syncthreads();
    m = fmaxf(fmaxf(sred[0], sred[1]), fmaxf(sred[2], sred[3]));
    __syncthreads();

    float ls = 0.f;
    for (int j = tid; j < cnt; j += 128) {
        float pv = expf(sc[j] - m);
        sc[j] = pv;
        ls += pv;
    }
    ls = warpSum(ls);
    if ((tid & 31) == 0) sred[tid >> 5] = ls;
    __syncthreads();
    float ssum = sred[0] + sred[1] + sred[2] + sred[3];

    int d = tid & 63, grp = tid >> 6;
    float acc = 0.f;
    for (int j = grp; j < cnt; j += 2)
        acc += sc[j] * g_qkv[((size_t)b * M_ + start + j) * (3 * C_) + 2 * C_ + h * D_ + d];
    oacc[tid] = acc;
    __syncthreads();

    float* dst = g_clsp + ((size_t)bh * 8 + chunk) * 66;
    if (tid < 64) dst[2 + tid] = oacc[tid] + oacc[tid + 64];
    if (tid == 0) { dst[0] = m; dst[1] = ssum; }
}

__global__ void attn_cls_comb_kernel() {
    int bh = blockIdx.x;             // 0..47
    int b = bh / H_, h = bh % H_;
    int d = threadIdx.x;             // 64
    const float* src = g_clsp + (size_t)bh * 8 * 66;
    float M = 0.f;
#pragma unroll
    for (int c = 0; c < 8; ++c) M = fmaxf(M, src[c * 66]);
    float denom = expf(-M);
    float o = 0.f;
#pragma unroll
    for (int c = 0; c < 8; ++c) {
        float w = expf(src[c * 66] - M);
        denom += src[c * 66 + 1] * w;
        o += src[c * 66 + 2 + d] * w;
    }
    g_att[(size_t)(b * M_) * C_ + h * D_ + d] = o / denom;
}

// Pad query: parallel over rows. grid (12, B), block 256.
__global__ void attn_pad_kernel() {
    int b = blockIdx.y;
    int cg = blockIdx.x;
    int tid = threadIdx.x;
    int cl = tid & 31;
    int rg = tid >> 5;
    int ch = cg * 32 + cl;
    const float* base = g_qkv + (size_t)b * M_ * (3 * C_) + 2 * C_ + ch;
    float acc = 0.f;
    for (int mrow = rg; mrow < 1025; mrow += 8)
        acc += base[(size_t)mrow * (3 * C_)];
    __shared__ float sm2[8][32];
    sm2[rg][cl] = acc;
    __syncthreads();
    if (tid < 32) {
        float a = 0.f;
#pragma unroll
        for (int rr = 0; rr < 8; ++rr) a += sm2[rr][tid];
        g_att[((size_t)b * M_ + 1025) * C_ + cg * 32 + tid] = a * (1.0f / 1026.0f);
    }
}

__global__ void concat_kernel() {
    int row = blockIdx.x;
    int b = row / CAT_, i = row % CAT_;
    const float* src = (i == 0) ? (g_h2 + (size_t)b * 1025 * C_)
                                : (g_tok + ((size_t)b * W_ + (i - 1)) * C_);
    float* dst = g_cat + (size_t)row * C_;
    for (int c = threadIdx.x; c < C_; c += blockDim.x) dst[c] = src[c];
}

// ---------------------------------------------------------------------------
// Launch
// ---------------------------------------------------------------------------
extern "C" void kernel_launch(void* const* d_in, const int* in_sizes, int n_in,
                              void* d_out, int out_size) {
    const float* x      = (const float*)d_in[0];
    const float* n1w    = (const float*)d_in[1];
    const float* n1b    = (const float*)d_in[2];
    const float* qkv_w  = (const float*)d_in[3];
    const float* proj_w = (const float*)d_in[4];
    const float* proj_b = (const float*)d_in[5];
    const float* n2w    = (const float*)d_in[6];
    const float* n2b    = (const float*)d_in[7];
    const float* pool_w = (const float*)d_in[8];
    const float* pool_b = (const float*)d_in[9];
    const float* n3w    = (const float*)d_in[10];
    const float* n3b    = (const float*)d_in[11];
    const float* fc1_w  = (const float*)d_in[12];
    const float* fc1_b  = (const float*)d_in[13];
    const float* fc2_w  = (const float*)d_in[14];
    const float* fc2_b  = (const float*)d_in[15];
    float* out = (float*)d_out;

    float *h1, *qkvp, *att, *res, *h2, *tok, *cat, *h3, *fc1o;
    cudaGetSymbolAddress((void**)&h1,   g_h1);
    cudaGetSymbolAddress((void**)&qkvp, g_qkv);
    cudaGetSymbolAddress((void**)&att,  g_att);
    cudaGetSymbolAddress((void**)&res,  g_res);
    cudaGetSymbolAddress((void**)&h2,   g_h2);
    cudaGetSymbolAddress((void**)&tok,  g_tok);
    cudaGetSymbolAddress((void**)&cat,  g_cat);
    cudaGetSymbolAddress((void**)&h3,   g_h3);
    cudaGetSymbolAddress((void**)&fc1o, g_fc1);

    static int smemSet = 0;
    if (!smemSet) {
        cudaFuncSetAttribute(tgemm_kernel,
                             cudaFuncAttributeMaxDynamicSharedMemorySize, TG_SMEM);
        smemSet = 1;
    }

    const int MROWS = B_ * M_;        // 8208
    const int PROWS = B_ * W_;        // 2048
    const int CROWS = B_ * CAT_;      // 2056

    ln_kernel<<<dim3(1025, B_), 128>>>(x, h1, n1w, n1b, 1025, M_);
    zero_pad_kernel<<<B_, C_>>>();

    tgemm_kernel<<<dim3(1152 / 64, (MROWS + 127) / 128), 256, TG_SMEM>>>(
        MROWS, 3 * C_, C_, h1, qkv_w, nullptr, nullptr, qkvp, 0, 0);

    attn_token_kernel<<<(B_ * H_ * NT_) / 8, 256>>>();
    attn_cls_part_kernel<<<dim3(8, B_ * H_), 128>>>();
    attn_cls_comb_kernel<<<B_ * H_, 64>>>();
    attn_pad_kernel<<<dim3(12, B_), 256>>>();

    tgemm_kernel<<<dim3(C_ / 64, (MROWS + 127) / 128), 256, TG_SMEM>>>(
        MROWS, C_, C_, att, proj_w, proj_b, h1, res, 0, 0);

    ln_kernel<<<dim3(1025, B_), 128>>>(res, h2, n2w, n2b, M_, 1025);

    // pool GEMM with fused window gather (A = g_h2)
    tgemm_kernel<<<dim3(C_ / 64, PROWS / 128), 256, TG_SMEM>>>(
        PROWS, C_, 9 * C_, h2, pool_w, pool_b, nullptr, tok, 0, 1);

    concat_kernel<<<B_ * CAT_, 128>>>();
    ln_kernel<<<dim3(CAT_, B_), 128>>>(cat, h3, n3w, n3b, CAT_, CAT_);

    tgemm_kernel<<<dim3(HID_ / 64, (CROWS + 127) / 128), 256, TG_SMEM>>>(
        CROWS, HID_, C_, h3, fc1_w, fc1_b, nullptr, fc1o, 1, 0);
    tgemm_kernel<<<dim3(C_ / 64, (CROWS + 127) / 128), 256, TG_SMEM>>>(
        CROWS, C_, HID_, fc1o, fc2_w, fc2_b, nullptr, out, 0, 0);
}